// round 1
// baseline (speedup 1.0000x reference)
#include <cuda_runtime.h>
#include <cuda_bf16.h>
#include <math.h>

#define Bd 64
#define Td 256
#define Ed 256
#define Ud 1024
#define Gd 3072   // 3*Ud

// Scratch (device globals: allocation-free rule)
__device__ float g_xe[Bd * Td * Ed];                 // 16.8 MB
__device__ float g_gx[2][(size_t)Bd * Td * Gd];      // 2 x 201 MB: precomputed x@W + b_in
__device__ float g_h[2][2][Bd * Ud];                 // [dir][parity][b*U]

// ---------------------------------------------------------------------------
// 1) Embedding gather: xe[b,t,:] = emb[x[b,t],:]
// ---------------------------------------------------------------------------
__global__ void k_embed(const int* __restrict__ x, const float* __restrict__ emb) {
    int bt = blockIdx.x;            // 0..B*T-1
    int tok = x[bt];
    g_xe[bt * Ed + threadIdx.x] = emb[tok * Ed + threadIdx.x];
}

// ---------------------------------------------------------------------------
// 2) Init hidden double buffers (parity 0) for both directions
// ---------------------------------------------------------------------------
__global__ void k_init(const float* __restrict__ hidden) {
    int i = blockIdx.x * blockDim.x + threadIdx.x;   // 65536 total
    float v = hidden[i];
    g_h[0][0][i] = v;
    g_h[1][0][i] = v;
}

// ---------------------------------------------------------------------------
// 3) Input GEMM: gx[dir] = xe (16384x256) @ W[dir] (256x3072) + b_in[dir]
//    Tiling: BM=64, BN=64, BK=32, 256 threads, 4x4 per thread
// ---------------------------------------------------------------------------
__global__ void k_ingemm(const float* __restrict__ Wf, const float* __restrict__ Wb,
                         const float* __restrict__ bf, const float* __restrict__ bb) {
    int dir = blockIdx.z;
    const float* W    = dir ? Wb : Wf;
    const float* bias = dir ? bb : bf;
    float* C = g_gx[dir];

    int n0 = blockIdx.x * 64;
    int m0 = blockIdx.y * 64;

    __shared__ float As[32][65];   // As[k][m], padded
    __shared__ float Bs[32][64];   // Bs[k][n]

    int tid = threadIdx.x;
    int tx = tid & 15, ty = tid >> 4;

    float acc[4][4] = {};

    for (int k0 = 0; k0 < Ed; k0 += 32) {
        // load A tile (64 rows x 32 k)
        #pragma unroll
        for (int i = 0; i < 8; i++) {
            int idx = tid + i * 256;
            int m = idx >> 5, k = idx & 31;
            As[k][m] = g_xe[(m0 + m) * Ed + k0 + k];
        }
        // load B tile (32 k x 64 n)
        #pragma unroll
        for (int i = 0; i < 8; i++) {
            int idx = tid + i * 256;
            int k = idx >> 6, n = idx & 63;
            Bs[k][n] = W[(size_t)(k0 + k) * Gd + n0 + n];
        }
        __syncthreads();

        #pragma unroll
        for (int k = 0; k < 32; k++) {
            float a0 = As[k][ty * 4 + 0];
            float a1 = As[k][ty * 4 + 1];
            float a2 = As[k][ty * 4 + 2];
            float a3 = As[k][ty * 4 + 3];
            float b0 = Bs[k][tx * 4 + 0];
            float b1 = Bs[k][tx * 4 + 1];
            float b2 = Bs[k][tx * 4 + 2];
            float b3 = Bs[k][tx * 4 + 3];
            acc[0][0] += a0 * b0; acc[0][1] += a0 * b1; acc[0][2] += a0 * b2; acc[0][3] += a0 * b3;
            acc[1][0] += a1 * b0; acc[1][1] += a1 * b1; acc[1][2] += a1 * b2; acc[1][3] += a1 * b3;
            acc[2][0] += a2 * b0; acc[2][1] += a2 * b1; acc[2][2] += a2 * b2; acc[2][3] += a2 * b3;
            acc[3][0] += a3 * b0; acc[3][1] += a3 * b1; acc[3][2] += a3 * b2; acc[3][3] += a3 * b3;
        }
        __syncthreads();
    }

    #pragma unroll
    for (int i = 0; i < 4; i++) {
        #pragma unroll
        for (int j = 0; j < 4; j++) {
            int n = n0 + tx * 4 + j;
            C[(size_t)(m0 + ty * 4 + i) * Gd + n] = acc[i][j] + bias[n];
        }
    }
}

// ---------------------------------------------------------------------------
// 4) One recurrence step (both directions in grid.z).
//    CTA: 256 threads, owns 16 h-columns (=> 48 gr columns across 3 gates).
//    gr = h_old @ U  (K=1024), then gates, masked update, write h_new + out.
// ---------------------------------------------------------------------------
__global__ void k_step(int s, const int* __restrict__ x,
                       const float* __restrict__ Uf, const float* __restrict__ Ubm,
                       const float* __restrict__ brf, const float* __restrict__ brb,
                       float* __restrict__ out) {
    int dir = blockIdx.z;
    int t = (dir == 0) ? s : (Td - 1 - s);
    const float* Umat = dir ? Ubm : Uf;
    const float* brec = dir ? brb : brf;
    const float* gx = g_gx[dir];
    const float* h_old = g_h[dir][s & 1];
    float* h_new = g_h[dir][(s + 1) & 1];

    int c0 = blockIdx.x * 16;

    __shared__ float hT[32][65];   // hT[k][b], padded
    __shared__ float Us[32][48];   // Us[k][gate*16 + c]

    int tid = threadIdx.x;
    int cc = tid & 15;            // h-column within block
    int r0 = (tid >> 4) * 4;      // 4 batch rows per thread

    float az[4] = {0.f, 0.f, 0.f, 0.f};
    float ar[4] = {0.f, 0.f, 0.f, 0.f};
    float ah[4] = {0.f, 0.f, 0.f, 0.f};

    for (int k0 = 0; k0 < Ud; k0 += 32) {
        // h tile: 64 rows x 32 k  (2048 elems)
        #pragma unroll
        for (int i = 0; i < 8; i++) {
            int idx = tid + i * 256;
            int b = idx >> 5, k = idx & 31;
            hT[k][b] = h_old[b * Ud + k0 + k];
        }
        // U tile: 32 k x 48 cols  (1536 elems)
        #pragma unroll
        for (int i = 0; i < 6; i++) {
            int idx = tid + i * 256;
            int k = idx / 48, j = idx - k * 48;
            int gate = j >> 4, c = j & 15;
            Us[k][j] = Umat[(size_t)(k0 + k) * Gd + gate * Ud + c0 + c];
        }
        __syncthreads();

        #pragma unroll
        for (int k = 0; k < 32; k++) {
            float uz = Us[k][cc];
            float ur = Us[k][16 + cc];
            float uh = Us[k][32 + cc];
            #pragma unroll
            for (int i = 0; i < 4; i++) {
                float hv = hT[k][r0 + i];
                az[i] += hv * uz;
                ar[i] += hv * ur;
                ah[i] += hv * uh;
            }
        }
        __syncthreads();
    }

    float bz = brec[c0 + cc];
    float br = brec[Ud + c0 + cc];
    float bh = brec[2 * Ud + c0 + cc];

    #pragma unroll
    for (int i = 0; i < 4; i++) {
        int b = r0 + i;
        size_t base = (size_t)(b * Td + t) * Gd + c0 + cc;
        float xz = gx[base];
        float xr = gx[base + Ud];
        float xh = gx[base + 2 * Ud];
        float ho = h_old[b * Ud + c0 + cc];

        float z = 1.f / (1.f + expf(-(xz + az[i] + bz)));
        float r = 1.f / (1.f + expf(-(xr + ar[i] + br)));
        float hh = tanhf(xh + r * (ah[i] + bh));
        float hn = z * ho + (1.f - z) * hh;
        if (x[b * Td + t] == 0) hn = ho;

        h_new[b * Ud + c0 + cc] = hn;
        out[(size_t)(b * Td + t) * (2 * Ud) + dir * Ud + c0 + cc] = hn;
    }
}

// ---------------------------------------------------------------------------
// 5) Projection: state = tanh([hf|hb] @ Wp + bp)   (final h at parity 0)
// ---------------------------------------------------------------------------
__global__ void k_proj(const float* __restrict__ Wp, const float* __restrict__ bp,
                       float* __restrict__ out) {
    float* state = out + (size_t)Bd * Td * 2 * Ud;
    int b = blockIdx.x;

    __shared__ float cat[2 * Ud];
    for (int i = threadIdx.x; i < Ud; i += blockDim.x) {
        cat[i]      = g_h[0][0][b * Ud + i];
        cat[Ud + i] = g_h[1][0][b * Ud + i];
    }
    __syncthreads();

    for (int u = threadIdx.x; u < Ud; u += 256) {
        float acc = bp[u];
        for (int k = 0; k < 2 * Ud; k++)
            acc += cat[k] * Wp[(size_t)k * Ud + u];
        state[b * Ud + u] = tanhf(acc);
    }
}

// ---------------------------------------------------------------------------
extern "C" void kernel_launch(void* const* d_in, const int* in_sizes, int n_in,
                              void* d_out, int out_size) {
    const int*   x      = (const int*)d_in[0];
    const float* hidden = (const float*)d_in[1];
    const float* emb    = (const float*)d_in[2];
    const float* Wf     = (const float*)d_in[3];
    const float* Uf     = (const float*)d_in[4];
    const float* bf_in  = (const float*)d_in[5];
    const float* bf_rec = (const float*)d_in[6];
    const float* Wb     = (const float*)d_in[7];
    const float* Ub     = (const float*)d_in[8];
    const float* bb_in  = (const float*)d_in[9];
    const float* bb_rec = (const float*)d_in[10];
    const float* Wp     = (const float*)d_in[11];
    const float* bp     = (const float*)d_in[12];
    float* out = (float*)d_out;

    k_embed<<<Bd * Td, 256>>>(x, emb);
    k_init<<<(Bd * Ud) / 256, 256>>>(hidden);

    dim3 gi(Gd / 64, (Bd * Td) / 64, 2);
    k_ingemm<<<gi, 256>>>(Wf, Wb, bf_in, bb_in);

    dim3 gs(Ud / 16, 1, 2);
    for (int s = 0; s < Td; s++) {
        k_step<<<gs, 256>>>(s, x, Uf, Ub, bf_rec, bb_rec, out);
    }

    k_proj<<<Bd, 256>>>(Wp, bp, out);
}

// round 3
// speedup vs baseline: 1.4046x; 1.4046x over previous
#include <cuda_runtime.h>
#include <math.h>

#define Bd 64
#define Td 256
#define Ed 256
#define Ud 1024
#define Gd 3072   // 3*Ud
#define NCTA_DIR 64
#define THREADS 256

// Scratch (device globals: allocation-free rule)
__device__ float g_xe[Bd * Td * Ed];
__device__ float g_gx[2][(size_t)Bd * Td * Gd];   // precomputed x@W + b_in
__device__ float g_h[2][2][Bd * Ud];              // [dir][parity][b*U]
__device__ unsigned g_cnt[2];                     // grid barrier arrive counters
__device__ unsigned g_gen[2];                     // grid barrier generations

// ---------------- f32x2 packed helpers (sm_100+) ----------------
__device__ __forceinline__ unsigned long long pack2(float lo, float hi) {
    unsigned long long r;
    asm("mov.b64 %0, {%1, %2};" : "=l"(r) : "f"(lo), "f"(hi));
    return r;
}
__device__ __forceinline__ void unpack2(unsigned long long v, float& lo, float& hi) {
    asm("mov.b64 {%0, %1}, %2;" : "=f"(lo), "=f"(hi) : "l"(v));
}
__device__ __forceinline__ void fma2(unsigned long long& acc,
                                     unsigned long long a, unsigned long long b) {
    asm("fma.rn.f32x2 %0, %1, %2, %0;" : "+l"(acc) : "l"(a), "l"(b));
}

// ---------------------------------------------------------------------------
// 1) Embedding gather
// ---------------------------------------------------------------------------
__global__ void k_embed(const int* __restrict__ x, const float* __restrict__ emb) {
    int bt = blockIdx.x;
    int tok = x[bt];
    g_xe[bt * Ed + threadIdx.x] = emb[tok * Ed + threadIdx.x];
}

// ---------------------------------------------------------------------------
// 2) Init hidden double buffers (parity 0), both directions
// ---------------------------------------------------------------------------
__global__ void k_init(const float* __restrict__ hidden) {
    int i = blockIdx.x * blockDim.x + threadIdx.x;
    float v = hidden[i];
    g_h[0][0][i] = v;
    g_h[1][0][i] = v;
}

// ---------------------------------------------------------------------------
// 3) Input GEMM with f32x2: gx[dir] = xe (16384x256) @ W (256x3072) + b_in
//    BM=64, BN=64, BK=32, 256 threads, 4x4 per thread (as 4x2 f32x2 pairs)
// ---------------------------------------------------------------------------
__global__ void k_ingemm(const float* __restrict__ Wf, const float* __restrict__ Wb,
                         const float* __restrict__ bf, const float* __restrict__ bb) {
    int dir = blockIdx.z;
    const float* W    = dir ? Wb : Wf;
    const float* bias = dir ? bb : bf;
    float* C = g_gx[dir];

    int n0 = blockIdx.x * 64;
    int m0 = blockIdx.y * 64;

    __shared__ float As[32][65];
    __shared__ float Bs[32][64];

    int tid = threadIdx.x;
    int tx = tid & 15, ty = tid >> 4;

    unsigned long long acc[4][2] = {};   // 4 m-rows x 2 n-pairs

    for (int k0 = 0; k0 < Ed; k0 += 32) {
        #pragma unroll
        for (int i = 0; i < 8; i++) {
            int idx = tid + i * 256;
            int m = idx >> 5, k = idx & 31;
            As[k][m] = g_xe[(m0 + m) * Ed + k0 + k];
        }
        #pragma unroll
        for (int i = 0; i < 8; i++) {
            int idx = tid + i * 256;
            int k = idx >> 6, n = idx & 63;
            Bs[k][n] = W[(size_t)(k0 + k) * Gd + n0 + n];
        }
        __syncthreads();

        #pragma unroll
        for (int k = 0; k < 32; k++) {
            unsigned long long b01 =
                *reinterpret_cast<const unsigned long long*>(&Bs[k][tx * 4]);
            unsigned long long b23 =
                *reinterpret_cast<const unsigned long long*>(&Bs[k][tx * 4 + 2]);
            #pragma unroll
            for (int i = 0; i < 4; i++) {
                float a = As[k][ty * 4 + i];
                unsigned long long ap = pack2(a, a);
                fma2(acc[i][0], ap, b01);
                fma2(acc[i][1], ap, b23);
            }
        }
        __syncthreads();
    }

    #pragma unroll
    for (int i = 0; i < 4; i++) {
        float v0, v1, v2, v3;
        unpack2(acc[i][0], v0, v1);
        unpack2(acc[i][1], v2, v3);
        int n = n0 + tx * 4;
        size_t row = (size_t)(m0 + ty * 4 + i) * Gd;
        C[row + n + 0] = v0 + bias[n + 0];
        C[row + n + 1] = v1 + bias[n + 1];
        C[row + n + 2] = v2 + bias[n + 2];
        C[row + n + 3] = v3 + bias[n + 3];
    }
}

// ---------------------------------------------------------------------------
// 4) Persistent recurrence kernel.
//    128 CTAs (64 per direction), 1 CTA/SM (forced by 213KB dynamic SMEM),
//    grid 128 <= 148 SMs => all CTAs co-resident => spin barrier is safe.
//    Each CTA keeps its 48-gate-col U slice resident in SMEM for all 256
//    steps. Per-direction software grid barrier between steps.
// ---------------------------------------------------------------------------
__global__ void __launch_bounds__(THREADS, 1)
k_recur(const int* __restrict__ x,
        const float* __restrict__ Uf, const float* __restrict__ Ubm,
        const float* __restrict__ brf, const float* __restrict__ brb,
        float* __restrict__ out) {
    extern __shared__ float sm[];
    float* Us = sm;                      // 48*1024 floats = 196608 B
    float* hB = sm + 48 * Ud;            // 2 x (32*66) floats (double-buffered h tile)

    int bx = blockIdx.x;
    int dir = bx >> 6;
    int c0 = (bx & 63) * 16;
    const float* Umat = dir ? Ubm : Uf;
    const float* brec = dir ? brb : brf;
    const float* gx = g_gx[dir];
    int tid = threadIdx.x;
    int cc = tid & 15;
    int bp = tid >> 4;                   // 0..15

    // Load U slice once: Us[k*48 + gate*16 + c] = U[k][gate*1024 + c0 + c]
    for (int idx = tid; idx < 48 * Ud; idx += THREADS) {
        int k = idx / 48, j = idx - k * 48;
        int gate = j >> 4, c = j & 15;
        Us[idx] = Umat[(size_t)k * Gd + gate * Ud + c0 + c];
    }

    float bz = brec[c0 + cc];
    float br_ = brec[Ud + c0 + cc];
    float bh = brec[2 * Ud + c0 + cc];

    unsigned* cnt = &g_cnt[dir];
    unsigned* gen = &g_gen[dir];

    __syncthreads();

    for (int s = 0; s < Td; s++) {
        int t = dir ? (Td - 1 - s) : s;
        const float* h_old = g_h[dir][s & 1];
        float* h_new = g_h[dir][(s + 1) & 1];

        unsigned long long az0 = 0, az1 = 0, ar0 = 0, ar1 = 0, ah0 = 0, ah1 = 0;

        // preload h tile 0 (transposed [k][b], row stride 66)
        #pragma unroll
        for (int i = 0; i < 8; i++) {
            int idx = tid + i * 256;
            int b = idx >> 5, k = idx & 31;
            hB[k * 66 + b] = h_old[b * Ud + k];
        }
        __syncthreads();

        for (int kt = 0; kt < 32; kt++) {
            const float* cur = hB + (kt & 1) * 2112;
            if (kt < 31) {               // prefetch next h tile into other buffer
                float* nxt = hB + ((kt + 1) & 1) * 2112;
                int k0 = (kt + 1) * 32;
                #pragma unroll
                for (int i = 0; i < 8; i++) {
                    int idx = tid + i * 256;
                    int b = idx >> 5, k = idx & 31;
                    nxt[k * 66 + b] = h_old[b * Ud + k0 + k];
                }
            }
            const float* ub = Us + kt * 32 * 48;
            #pragma unroll
            for (int k = 0; k < 32; k++) {
                float uz = ub[k * 48 + cc];
                float ur = ub[k * 48 + 16 + cc];
                float uh = ub[k * 48 + 32 + cc];
                unsigned long long uz2 = pack2(uz, uz);
                unsigned long long ur2 = pack2(ur, ur);
                unsigned long long uh2 = pack2(uh, uh);
                unsigned long long h0 =
                    *reinterpret_cast<const unsigned long long*>(cur + k * 66 + 4 * bp);
                unsigned long long h1 =
                    *reinterpret_cast<const unsigned long long*>(cur + k * 66 + 4 * bp + 2);
                fma2(az0, h0, uz2); fma2(ar0, h0, ur2); fma2(ah0, h0, uh2);
                fma2(az1, h1, uz2); fma2(ar1, h1, ur2); fma2(ah1, h1, uh2);
            }
            __syncthreads();
        }

        float azf[4], arf[4], ahf[4];
        unpack2(az0, azf[0], azf[1]); unpack2(az1, azf[2], azf[3]);
        unpack2(ar0, arf[0], arf[1]); unpack2(ar1, arf[2], arf[3]);
        unpack2(ah0, ahf[0], ahf[1]); unpack2(ah1, ahf[2], ahf[3]);

        #pragma unroll
        for (int i = 0; i < 4; i++) {
            int b = 4 * bp + i;
            size_t base = ((size_t)(b * Td + t)) * Gd + c0 + cc;
            float xz = gx[base];
            float xr = gx[base + Ud];
            float xh = gx[base + 2 * Ud];
            float ho = h_old[b * Ud + c0 + cc];
            float z = 1.f / (1.f + __expf(-(xz + azf[i] + bz)));
            float r = 1.f / (1.f + __expf(-(xr + arf[i] + br_)));
            float hh = tanhf(xh + r * (ahf[i] + bh));
            float hn = z * ho + (1.f - z) * hh;
            if (x[b * Td + t] == 0) hn = ho;
            h_new[b * Ud + c0 + cc] = hn;
            out[((size_t)(b * Td + t)) * (2 * Ud) + dir * Ud + c0 + cc] = hn;
        }

        // per-direction grid barrier (all CTAs resident: 1 CTA/SM, grid=128<=148)
        __syncthreads();
        if (tid == 0) {
            unsigned my;
            asm volatile("ld.acquire.gpu.u32 %0, [%1];" : "=r"(my) : "l"(gen));
            __threadfence();
            unsigned prev = atomicAdd(cnt, 1u);
            if (prev == NCTA_DIR - 1) {
                atomicExch(cnt, 0u);
                __threadfence();
                atomicAdd(gen, 1u);
            } else {
                unsigned cg;
                do {
                    __nanosleep(64);
                    asm volatile("ld.acquire.gpu.u32 %0, [%1];" : "=r"(cg) : "l"(gen));
                } while (cg == my);
            }
        }
        __syncthreads();
    }
}

// ---------------------------------------------------------------------------
// 5) Projection: state = tanh([hf|hb] @ Wp + bp)  (final h at parity 0)
// ---------------------------------------------------------------------------
__global__ void k_proj(const float* __restrict__ Wp, const float* __restrict__ bp,
                       float* __restrict__ out) {
    float* state = out + (size_t)Bd * Td * 2 * Ud;
    int b = blockIdx.x;

    __shared__ float cat[2 * Ud];
    for (int i = threadIdx.x; i < Ud; i += blockDim.x) {
        cat[i]      = g_h[0][0][b * Ud + i];
        cat[Ud + i] = g_h[1][0][b * Ud + i];
    }
    __syncthreads();

    for (int u = threadIdx.x; u < Ud; u += 256) {
        float acc = bp[u];
        for (int k = 0; k < 2 * Ud; k++)
            acc += cat[k] * Wp[(size_t)k * Ud + u];
        state[b * Ud + u] = tanhf(acc);
    }
}

// ---------------------------------------------------------------------------
extern "C" void kernel_launch(void* const* d_in, const int* in_sizes, int n_in,
                              void* d_out, int out_size) {
    const int*   x      = (const int*)d_in[0];
    const float* hidden = (const float*)d_in[1];
    const float* emb    = (const float*)d_in[2];
    const float* Wf     = (const float*)d_in[3];
    const float* Uf     = (const float*)d_in[4];
    const float* bf_in  = (const float*)d_in[5];
    const float* bf_rec = (const float*)d_in[6];
    const float* Wb     = (const float*)d_in[7];
    const float* Ub     = (const float*)d_in[8];
    const float* bb_in  = (const float*)d_in[9];
    const float* bb_rec = (const float*)d_in[10];
    const float* Wp     = (const float*)d_in[11];
    const float* bp     = (const float*)d_in[12];
    float* out = (float*)d_out;

    const int smem_bytes = (48 * Ud + 2 * 32 * 66) * sizeof(float);  // 213504
    cudaFuncSetAttribute(k_recur, cudaFuncAttributeMaxDynamicSharedMemorySize,
                         smem_bytes);

    k_embed<<<Bd * Td, 256>>>(x, emb);
    k_init<<<(Bd * Ud) / 256, 256>>>(hidden);

    dim3 gi(Gd / 64, (Bd * Td) / 64, 2);
    k_ingemm<<<gi, 256>>>(Wf, Wb, bf_in, bb_in);

    k_recur<<<2 * NCTA_DIR, THREADS, smem_bytes>>>(x, Uf, Ub, bf_rec, bb_rec, out);

    k_proj<<<Bd, 256>>>(Wp, bp, out);
}

// round 5
// speedup vs baseline: 1.6287x; 1.1595x over previous
#include <cuda_runtime.h>
#include <cuda_bf16.h>
#include <math.h>

#define Bd 64
#define Td 256
#define Ed 256
#define Ud 1024
#define Gd 3072   // 3*Ud
#define NCTA_DIR 64
#define THREADS 256
#define NCHUNK 64          // 1024 / 16
#define USTRIDE 1032       // padded k-stride for U smem (conflict-free B frag LDS)
#define ASTRIDE 24         // padded k-stride for A stage smem (conflict-free A frag LDS)

// ---------------- device scratch (allocation-free rule) ----------------
__device__ float g_xe[Bd * Td * Ed];
__device__ float g_gx[2][(size_t)Bd * Td * Gd];          // x@W + b_in
__device__ float g_h[2][2][Bd][Ud];                      // [dir][parity][b][u] fp32
__device__ __nv_bfloat16 g_hbf[2][2][2][Bd][Ud];         // [dir][parity][hi/lo][b][u]
__device__ __nv_bfloat16 g_Ubf[2][2][Gd][Ud];            // [dir][hi/lo][n][k] (k-contig)
__device__ unsigned g_cnt[2];
__device__ unsigned g_gen[2];

// ---------------- helpers ----------------
__device__ __forceinline__ unsigned long long pack2(float lo, float hi) {
    unsigned long long r;
    asm("mov.b64 %0, {%1, %2};" : "=l"(r) : "f"(lo), "f"(hi));
    return r;
}
__device__ __forceinline__ void unpack2(unsigned long long v, float& lo, float& hi) {
    asm("mov.b64 {%0, %1}, %2;" : "=f"(lo), "=f"(hi) : "l"(v));
}
__device__ __forceinline__ void fma2(unsigned long long& acc,
                                     unsigned long long a, unsigned long long b) {
    asm("fma.rn.f32x2 %0, %1, %2, %0;" : "+l"(acc) : "l"(a), "l"(b));
}

#define MMA_BF16(C, A0, A1, A2, A3, B0, B1)                                   \
    asm volatile(                                                             \
        "mma.sync.aligned.m16n8k16.row.col.f32.bf16.bf16.f32 "                \
        "{%0,%1,%2,%3}, {%4,%5,%6,%7}, {%8,%9}, {%0,%1,%2,%3};"               \
        : "+f"(C[0]), "+f"(C[1]), "+f"(C[2]), "+f"(C[3])                      \
        : "r"(A0), "r"(A1), "r"(A2), "r"(A3), "r"(B0), "r"(B1))

__device__ __forceinline__ float sigf(float a) {
    return 1.f / (1.f + __expf(-a));
}

// ---------------------------------------------------------------------------
// 1) Embedding gather
// ---------------------------------------------------------------------------
__global__ void k_embed(const int* __restrict__ x, const float* __restrict__ emb) {
    int bt = blockIdx.x;
    int tok = x[bt];
    g_xe[bt * Ed + threadIdx.x] = emb[tok * Ed + threadIdx.x];
}

// ---------------------------------------------------------------------------
// 2) Init hidden: fp32 double buffers (parity 0) + bf16 hi/lo split
// ---------------------------------------------------------------------------
__global__ void k_init(const float* __restrict__ hidden) {
    int i = blockIdx.x * blockDim.x + threadIdx.x;   // 65536
    float v = hidden[i];
    int b = i >> 10, k = i & 1023;
    g_h[0][0][b][k] = v;
    g_h[1][0][b][k] = v;
    __nv_bfloat16 hi = __float2bfloat16(v);
    __nv_bfloat16 lo = __float2bfloat16(v - __bfloat162float(hi));
    g_hbf[0][0][0][b][k] = hi; g_hbf[0][0][1][b][k] = lo;
    g_hbf[1][0][0][b][k] = hi; g_hbf[1][0][1][b][k] = lo;
}

// ---------------------------------------------------------------------------
// 3) U split+transpose: g_Ubf[dir][hi/lo][n][k] from U[k][n] (32x32 smem tiles)
// ---------------------------------------------------------------------------
__global__ void k_usplit(const float* __restrict__ Uf, const float* __restrict__ Ub) {
    __shared__ float tile[32][33];
    int dir = blockIdx.z;
    const float* U = dir ? Ub : Uf;
    int n0 = blockIdx.x * 32, k0 = blockIdx.y * 32;

    for (int i = threadIdx.y; i < 32; i += 8)
        tile[i][threadIdx.x] = U[(size_t)(k0 + i) * Gd + n0 + threadIdx.x];
    __syncthreads();
    for (int i = threadIdx.y; i < 32; i += 8) {
        float u = tile[threadIdx.x][i];              // (k = k0+tx, n = n0+i)
        __nv_bfloat16 hi = __float2bfloat16(u);
        __nv_bfloat16 lo = __float2bfloat16(u - __bfloat162float(hi));
        g_Ubf[dir][0][n0 + i][k0 + threadIdx.x] = hi;
        g_Ubf[dir][1][n0 + i][k0 + threadIdx.x] = lo;
    }
}

// ---------------------------------------------------------------------------
// 4) Input GEMM (f32x2): gx = xe (16384x256) @ W (256x3072) + b_in
// ---------------------------------------------------------------------------
__global__ void k_ingemm(const float* __restrict__ Wf, const float* __restrict__ Wb,
                         const float* __restrict__ bf, const float* __restrict__ bb) {
    int dir = blockIdx.z;
    const float* W    = dir ? Wb : Wf;
    const float* bias = dir ? bb : bf;
    float* C = g_gx[dir];

    int n0 = blockIdx.x * 64;
    int m0 = blockIdx.y * 64;

    __shared__ float As_[32][65];
    __shared__ float Bs_[32][64];

    int tid = threadIdx.x;
    int tx = tid & 15, ty = tid >> 4;

    unsigned long long acc[4][2] = {};

    for (int k0 = 0; k0 < Ed; k0 += 32) {
        #pragma unroll
        for (int i = 0; i < 8; i++) {
            int idx = tid + i * 256;
            int m = idx >> 5, k = idx & 31;
            As_[k][m] = g_xe[(m0 + m) * Ed + k0 + k];
        }
        #pragma unroll
        for (int i = 0; i < 8; i++) {
            int idx = tid + i * 256;
            int k = idx >> 6, n = idx & 63;
            Bs_[k][n] = W[(size_t)(k0 + k) * Gd + n0 + n];
        }
        __syncthreads();

        #pragma unroll
        for (int k = 0; k < 32; k++) {
            unsigned long long b01 =
                *reinterpret_cast<const unsigned long long*>(&Bs_[k][tx * 4]);
            unsigned long long b23 =
                *reinterpret_cast<const unsigned long long*>(&Bs_[k][tx * 4 + 2]);
            #pragma unroll
            for (int i = 0; i < 4; i++) {
                float a = As_[k][ty * 4 + i];
                unsigned long long ap = pack2(a, a);
                fma2(acc[i][0], ap, b01);
                fma2(acc[i][1], ap, b23);
            }
        }
        __syncthreads();
    }

    #pragma unroll
    for (int i = 0; i < 4; i++) {
        float v0, v1, v2, v3;
        unpack2(acc[i][0], v0, v1);
        unpack2(acc[i][1], v2, v3);
        int n = n0 + tx * 4;
        size_t row = (size_t)(m0 + ty * 4 + i) * Gd;
        C[row + n + 0] = v0 + bias[n + 0];
        C[row + n + 1] = v1 + bias[n + 1];
        C[row + n + 2] = v2 + bias[n + 2];
        C[row + n + 3] = v3 + bias[n + 3];
    }
}

// ---------------------------------------------------------------------------
// 5) Persistent recurrence with bf16 3-split tensor-core step GEMM.
//    128 CTAs (64/dir), 1 CTA/SM (210KB dyn smem). CTA owns 16 h-cols
//    (48 gate-cols). U slice resident in smem as bf16 hi/lo. Per chunk of
//    k16: stage h hi/lo tile to smem, mma.sync m16n8k16 x9 per warp
//    (3 gate tiles x 3 split products). Grid barrier per step per dir.
// ---------------------------------------------------------------------------
__global__ void __launch_bounds__(THREADS, 1)
k_recur(const int* __restrict__ x,
        const float* __restrict__ brf, const float* __restrict__ brb,
        float* __restrict__ out) {
    extern __shared__ unsigned char smraw[];
    __nv_bfloat16* Us = (__nv_bfloat16*)smraw;                 // [2][48][USTRIDE]
    __nv_bfloat16* Ast = (__nv_bfloat16*)(smraw + 2 * 48 * USTRIDE * 2); // [2buf][2][64][ASTRIDE]

    int bx = blockIdx.x;
    int dir = bx >> 6;
    int c0 = (bx & 63) * 16;
    const float* brec = dir ? brb : brf;
    const float* gx = g_gx[dir];
    int tid = threadIdx.x;
    int wid = tid >> 5, lane = tid & 31;
    int mt = wid & 3, nh = wid >> 2;
    int g = lane >> 2, tg = lane & 3;

    // load U slice (bf16 hi/lo) once
    for (int idx = tid; idx < 2 * 48 * 1024; idx += THREADS) {
        int s = idx / 49152;
        int rem = idx - s * 49152;
        int j = rem >> 10;
        int k = rem & 1023;
        int gate = j >> 4, c = j & 15;
        Us[(s * 48 + j) * USTRIDE + k] = g_Ubf[dir][s][gate * 1024 + c0 + c][k];
    }

    // per-thread output coordinates
    int rl = mt * 16 + g, rh = rl + 8;           // batch rows
    int cb = c0 + nh * 8 + 2 * tg;               // h-col pair base (even)

    // recurrent biases (once)
    float2 Bz = *(const float2*)&brec[cb];
    float2 Br = *(const float2*)&brec[Ud + cb];
    float2 Bh = *(const float2*)&brec[2 * Ud + cb];

    // A stage coords
    int sr = tid >> 2;                // 0..63 row
    int sq = (tid & 3) * 4;           // k quad within chunk

    unsigned* cnt = &g_cnt[dir];
    unsigned* gen = &g_gen[dir];

    __syncthreads();

    for (int s = 0; s < Td; s++) {
        int t = dir ? (Td - 1 - s) : s;
        int par = s & 1;

        // ---- prefetch epilogue operands (independent of GEMM) ----
        size_t gl = (size_t)(rl * Td + t) * Gd + cb;
        size_t gh = (size_t)(rh * Td + t) * Gd + cb;
        float2 gz_l = __ldcg((const float2*)&gx[gl]);
        float2 gr_l = __ldcg((const float2*)&gx[gl + Ud]);
        float2 gh_l = __ldcg((const float2*)&gx[gl + 2 * Ud]);
        float2 gz_h = __ldcg((const float2*)&gx[gh]);
        float2 gr_h = __ldcg((const float2*)&gx[gh + Ud]);
        float2 gh_h = __ldcg((const float2*)&gx[gh + 2 * Ud]);
        float2 ho_l = __ldcg((const float2*)&g_h[dir][par][rl][cb]);
        float2 ho_h = __ldcg((const float2*)&g_h[dir][par][rh][cb]);
        int xl = __ldcg(&x[rl * Td + t]);
        int xh = __ldcg(&x[rh * Td + t]);

        float C0[4] = {0.f, 0.f, 0.f, 0.f};   // z tile
        float C1[4] = {0.f, 0.f, 0.f, 0.f};   // r tile
        float C2[4] = {0.f, 0.f, 0.f, 0.f};   // h~ tile

        const __nv_bfloat16* hbf_hi = &g_hbf[dir][par][0][0][0];
        const __nv_bfloat16* hbf_lo = &g_hbf[dir][par][1][0][0];

        // stage chunk 0
        {
            uint2 vhi = __ldcg((const uint2*)&hbf_hi[sr * Ud + sq]);
            uint2 vlo = __ldcg((const uint2*)&hbf_lo[sr * Ud + sq]);
            *(uint2*)&Ast[((0 * 2 + 0) * 64 + sr) * ASTRIDE + sq] = vhi;
            *(uint2*)&Ast[((0 * 2 + 1) * 64 + sr) * ASTRIDE + sq] = vlo;
        }
        __syncthreads();

        for (int ch = 0; ch < NCHUNK; ch++) {
            int buf = ch & 1;
            if (ch < NCHUNK - 1) {
                int k0n = (ch + 1) * 16;
                uint2 vhi = __ldcg((const uint2*)&hbf_hi[sr * Ud + k0n + sq]);
                uint2 vlo = __ldcg((const uint2*)&hbf_lo[sr * Ud + k0n + sq]);
                int bn = buf ^ 1;
                *(uint2*)&Ast[((bn * 2 + 0) * 64 + sr) * ASTRIDE + sq] = vhi;
                *(uint2*)&Ast[((bn * 2 + 1) * 64 + sr) * ASTRIDE + sq] = vlo;
            }

            // A fragments (hi, lo)
            const __nv_bfloat16* ah = &Ast[(buf * 2 + 0) * 64 * ASTRIDE];
            const __nv_bfloat16* al = &Ast[(buf * 2 + 1) * 64 * ASTRIDE];
            unsigned ahi0 = *(const unsigned*)&ah[(mt * 16 + g) * ASTRIDE + 2 * tg];
            unsigned ahi1 = *(const unsigned*)&ah[(mt * 16 + g + 8) * ASTRIDE + 2 * tg];
            unsigned ahi2 = *(const unsigned*)&ah[(mt * 16 + g) * ASTRIDE + 2 * tg + 8];
            unsigned ahi3 = *(const unsigned*)&ah[(mt * 16 + g + 8) * ASTRIDE + 2 * tg + 8];
            unsigned alo0 = *(const unsigned*)&al[(mt * 16 + g) * ASTRIDE + 2 * tg];
            unsigned alo1 = *(const unsigned*)&al[(mt * 16 + g + 8) * ASTRIDE + 2 * tg];
            unsigned alo2 = *(const unsigned*)&al[(mt * 16 + g) * ASTRIDE + 2 * tg + 8];
            unsigned alo3 = *(const unsigned*)&al[(mt * 16 + g + 8) * ASTRIDE + 2 * tg + 8];

            int k0 = ch * 16;
            #pragma unroll
            for (int gt = 0; gt < 3; gt++) {
                int nt = gt * 2 + nh;                 // ntile
                const __nv_bfloat16* uh = &Us[(0 * 48 + nt * 8 + g) * USTRIDE + k0];
                const __nv_bfloat16* ul = &Us[(1 * 48 + nt * 8 + g) * USTRIDE + k0];
                unsigned bhi0 = *(const unsigned*)&uh[2 * tg];
                unsigned bhi1 = *(const unsigned*)&uh[2 * tg + 8];
                unsigned blo0 = *(const unsigned*)&ul[2 * tg];
                unsigned blo1 = *(const unsigned*)&ul[2 * tg + 8];
                float* Cp = (gt == 0) ? C0 : (gt == 1) ? C1 : C2;
                MMA_BF16(Cp, ahi0, ahi1, ahi2, ahi3, bhi0, bhi1);
                MMA_BF16(Cp, ahi0, ahi1, ahi2, ahi3, blo0, blo1);
                MMA_BF16(Cp, alo0, alo1, alo2, alo3, bhi0, bhi1);
            }
            __syncthreads();
        }

        // ---- epilogue: gates for 2x2 outputs ----
        float hn[4];
        {
            float z0 = sigf(gz_l.x + C0[0] + Bz.x);
            float z1 = sigf(gz_l.y + C0[1] + Bz.y);
            float r0 = sigf(gr_l.x + C1[0] + Br.x);
            float r1 = sigf(gr_l.y + C1[1] + Br.y);
            float t0 = tanhf(gh_l.x + r0 * (C2[0] + Bh.x));
            float t1 = tanhf(gh_l.y + r1 * (C2[1] + Bh.y));
            hn[0] = z0 * ho_l.x + (1.f - z0) * t0;
            hn[1] = z1 * ho_l.y + (1.f - z1) * t1;
            if (xl == 0) { hn[0] = ho_l.x; hn[1] = ho_l.y; }

            float z2 = sigf(gz_h.x + C0[2] + Bz.x);
            float z3 = sigf(gz_h.y + C0[3] + Bz.y);
            float r2 = sigf(gr_h.x + C1[2] + Br.x);
            float r3 = sigf(gr_h.y + C1[3] + Br.y);
            float t2 = tanhf(gh_h.x + r2 * (C2[2] + Bh.x));
            float t3 = tanhf(gh_h.y + r3 * (C2[3] + Bh.y));
            hn[2] = z2 * ho_h.x + (1.f - z2) * t2;
            hn[3] = z3 * ho_h.y + (1.f - z3) * t3;
            if (xh == 0) { hn[2] = ho_h.x; hn[3] = ho_h.y; }
        }

        int pn = par ^ 1;
        *(float2*)&g_h[dir][pn][rl][cb] = make_float2(hn[0], hn[1]);
        *(float2*)&g_h[dir][pn][rh][cb] = make_float2(hn[2], hn[3]);

        #pragma unroll
        for (int rr = 0; rr < 2; rr++) {
            int b = rr ? rh : rl;
            float v0 = hn[rr * 2], v1 = hn[rr * 2 + 1];
            __nv_bfloat16 h0 = __float2bfloat16(v0);
            __nv_bfloat16 h1 = __float2bfloat16(v1);
            __nv_bfloat16 l0 = __float2bfloat16(v0 - __bfloat162float(h0));
            __nv_bfloat16 l1 = __float2bfloat16(v1 - __bfloat162float(h1));
            __nv_bfloat162 hp; hp.x = h0; hp.y = h1;
            __nv_bfloat162 lp; lp.x = l0; lp.y = l1;
            *(__nv_bfloat162*)&g_hbf[dir][pn][0][b][cb] = hp;
            *(__nv_bfloat162*)&g_hbf[dir][pn][1][b][cb] = lp;
            *(float2*)&out[(size_t)(b * Td + t) * (2 * Ud) + dir * Ud + cb] =
                make_float2(v0, v1);
        }

        // ---- per-direction grid barrier ----
        __syncthreads();
        if (tid == 0) {
            unsigned my;
            asm volatile("ld.acquire.gpu.u32 %0, [%1];" : "=r"(my) : "l"(gen));
            __threadfence();
            unsigned prev = atomicAdd(cnt, 1u);
            if (prev == NCTA_DIR - 1) {
                atomicExch(cnt, 0u);
                __threadfence();
                atomicAdd(gen, 1u);
            } else {
                unsigned cg;
                do {
                    __nanosleep(64);
                    asm volatile("ld.acquire.gpu.u32 %0, [%1];" : "=r"(cg) : "l"(gen));
                } while (cg == my);
            }
        }
        __syncthreads();
    }
}

// ---------------------------------------------------------------------------
// 6) Projection: state = tanh([hf|hb] @ Wp + bp)  (final h at parity 0)
// ---------------------------------------------------------------------------
__global__ void k_proj(const float* __restrict__ Wp, const float* __restrict__ bp,
                       float* __restrict__ out) {
    float* state = out + (size_t)Bd * Td * 2 * Ud;
    int b = blockIdx.x;

    __shared__ float cat[2 * Ud];
    for (int i = threadIdx.x; i < Ud; i += blockDim.x) {
        cat[i]      = g_h[0][0][b][i];
        cat[Ud + i] = g_h[1][0][b][i];
    }
    __syncthreads();

    for (int u = threadIdx.x; u < Ud; u += 256) {
        float acc = bp[u];
        for (int k = 0; k < 2 * Ud; k++)
            acc += cat[k] * Wp[(size_t)k * Ud + u];
        state[b * Ud + u] = tanhf(acc);
    }
}

// ---------------------------------------------------------------------------
extern "C" void kernel_launch(void* const* d_in, const int* in_sizes, int n_in,
                              void* d_out, int out_size) {
    const int*   x      = (const int*)d_in[0];
    const float* hidden = (const float*)d_in[1];
    const float* emb    = (const float*)d_in[2];
    const float* Wf     = (const float*)d_in[3];
    const float* Uf     = (const float*)d_in[4];
    const float* bf_in  = (const float*)d_in[5];
    const float* bf_rec = (const float*)d_in[6];
    const float* Wb     = (const float*)d_in[7];
    const float* Ub     = (const float*)d_in[8];
    const float* bb_in  = (const float*)d_in[9];
    const float* bb_rec = (const float*)d_in[10];
    const float* Wp     = (const float*)d_in[11];
    const float* bp     = (const float*)d_in[12];
    float* out = (float*)d_out;

    const int smem_bytes = (2 * 48 * USTRIDE + 2 * 2 * 64 * ASTRIDE) * 2; // 210432
    cudaFuncSetAttribute(k_recur, cudaFuncAttributeMaxDynamicSharedMemorySize,
                         smem_bytes);

    k_embed<<<Bd * Td, 256>>>(x, emb);
    k_init<<<(Bd * Ud) / 256, 256>>>(hidden);

    dim3 gu(Gd / 32, Ud / 32, 2);
    k_usplit<<<gu, dim3(32, 8)>>>(Uf, Ub);

    dim3 gi(Gd / 64, (Bd * Td) / 64, 2);
    k_ingemm<<<gi, 256>>>(Wf, Wb, bf_in, bb_in);

    k_recur<<<2 * NCTA_DIR, THREADS, smem_bytes>>>(x, bf_rec, bb_rec, out);

    k_proj<<<Bd, 256>>>(Wp, bp, out);
}